// round 1
// baseline (speedup 1.0000x reference)
#include <cuda_runtime.h>
#include <math.h>

#define NROWS 65536
#define KDIM  512
#define A3    64
#define CWIN  16
#define DTOW  8
#define PLEN  96

// ---------------- scratch (device globals; no allocations allowed) ----------
__device__ float g_t  [(size_t)NROWS * A3];            // 16 MB
__device__ float g_rep[(size_t)NROWS * A3];            // 16 MB
__device__ float g_h  [(size_t)DTOW * NROWS * A3];     // 128 MB
__device__ float g_y  [(size_t)DTOW * NROWS * PLEN];   // 192 MB
__device__ float g_sum[DTOW * A3];
__device__ float g_sq [DTOW * A3];
__device__ float g_scale[DTOW * A3];
__device__ float g_shift[DTOW * A3];

// ---------------- K1: t = normalize(x @ shuzhihua) --------------------------
// 128x64 output tile / block, 256 threads (16x16), 8x4 micro-tile, BK=32.
__global__ void __launch_bounds__(256) k1_gemm_norm(const float* __restrict__ x,
                                                    const float* __restrict__ w) {
    __shared__ float As[128][33];
    __shared__ float Bs[32][64];
    __shared__ float rnorm[128];
    const int tid = threadIdx.x;
    const int tx = tid & 15, ty = tid >> 4;
    const int r0 = blockIdx.x * 128;

    float acc[8][4];
#pragma unroll
    for (int rr = 0; rr < 8; rr++)
#pragma unroll
        for (int cc = 0; cc < 4; cc++) acc[rr][cc] = 0.f;

    for (int k0 = 0; k0 < KDIM; k0 += 32) {
        // A chunk: 128 rows x 32 k  (1024 float4, 4 per thread)
#pragma unroll
        for (int i = 0; i < 4; i++) {
            int idx = tid + i * 256;
            int row = idx >> 3, kq = idx & 7;
            float4 v = *(const float4*)&x[(size_t)(r0 + row) * KDIM + k0 + kq * 4];
            As[row][kq * 4 + 0] = v.x; As[row][kq * 4 + 1] = v.y;
            As[row][kq * 4 + 2] = v.z; As[row][kq * 4 + 3] = v.w;
        }
        // B chunk: 32 x 64  (512 float4, 2 per thread)
#pragma unroll
        for (int i = 0; i < 2; i++) {
            int idx = tid + i * 256;
            int row = idx >> 4, kq = idx & 15;
            *(float4*)&Bs[row][kq * 4] =
                *(const float4*)&w[(size_t)(k0 + row) * A3 + kq * 4];
        }
        __syncthreads();
#pragma unroll 8
        for (int k = 0; k < 32; k++) {
            float4 bv = *(const float4*)&Bs[k][tx * 4];
            float b0 = bv.x, b1 = bv.y, b2 = bv.z, b3 = bv.w;
            float a[8];
#pragma unroll
            for (int rr = 0; rr < 8; rr++) a[rr] = As[ty * 8 + rr][k];
#pragma unroll
            for (int rr = 0; rr < 8; rr++) {
                acc[rr][0] += a[rr] * b0; acc[rr][1] += a[rr] * b1;
                acc[rr][2] += a[rr] * b2; acc[rr][3] += a[rr] * b3;
            }
        }
        __syncthreads();
    }
    // row L2 norms (64 cols fully inside the block)
    if (tid < 128) rnorm[tid] = 0.f;
    __syncthreads();
#pragma unroll
    for (int rr = 0; rr < 8; rr++) {
        float p = acc[rr][0] * acc[rr][0] + acc[rr][1] * acc[rr][1]
                + acc[rr][2] * acc[rr][2] + acc[rr][3] * acc[rr][3];
        atomicAdd(&rnorm[ty * 8 + rr], p);
    }
    __syncthreads();
#pragma unroll
    for (int rr = 0; rr < 8; rr++) {
        float s = 1.f / fmaxf(sqrtf(rnorm[ty * 8 + rr]), 1e-12f);
        float4 o = make_float4(acc[rr][0] * s, acc[rr][1] * s,
                               acc[rr][2] * s, acc[rr][3] * s);
        *(float4*)&g_t[(size_t)(r0 + ty * 8 + rr) * A3 + tx * 4] = o;
    }
}

// ---------------- K2: windowed FIR sum over C=16 rows ------------------------
__global__ void __launch_bounds__(256) k2_window(const float* __restrict__ lw,
                                                 const float* __restrict__ lb,
                                                 float* __restrict__ rep_out) {
    __shared__ float ts[143 * 64];
    __shared__ float lws[16 * 64];
    __shared__ float sb[64];
    const int tid = threadIdx.x;
    const int r0 = blockIdx.x * 128;
    const int base = (r0 >= 15) ? (r0 - 15) : 0;
    const int nrows = r0 + 128 - base;

    for (int i = tid; i < nrows * 16; i += 256)
        ((float4*)ts)[i] = *(const float4*)&g_t[(size_t)base * A3 + (size_t)i * 4];
    for (int i = tid; i < 256; i += 256)
        ((float4*)lws)[i] = ((const float4*)lw)[i];
    if (tid < 64) {
        float s = 0.f;
#pragma unroll
        for (int j = 0; j < 16; j++) s += lb[j * 64 + tid];
        sb[tid] = s;
    }
    __syncthreads();

    const int c = tid & 63;
    const int rg = tid >> 6;  // 0..3, 32 rows each
    float lwr[16];
#pragma unroll
    for (int j = 0; j < 16; j++) lwr[j] = lws[j * 64 + c];
    const float sbc = sb[c];

    for (int rr = 0; rr < 32; rr++) {
        int i = r0 + rg * 32 + rr;
        float accv = sbc;
        if (i >= 15) {
            int off = i - 15 - base;
#pragma unroll
            for (int j = 0; j < 16; j++) accv += lwr[j] * ts[(off + j) * 64 + c];
        } else {  // prefix padding: idx = min(j, i)
#pragma unroll
            for (int j = 0; j < 16; j++) {
                int s = (j < i) ? j : i;
                accv += lwr[j] * ts[s * 64 + c];
            }
        }
        g_rep[(size_t)i * A3 + c] = accv;
        if (rep_out) rep_out[(size_t)i * A3 + c] = accv;
    }
}

// ---------------- zero BN accumulators (must run inside the graph) -----------
__global__ void kz_zero() {
    int i = threadIdx.x;
    if (i < DTOW * A3) { g_sum[i] = 0.f; g_sq[i] = 0.f; }
}

// ---------------- K3: h[d] = rep @ W1[d] + b1[d]; accumulate BN stats --------
__global__ void __launch_bounds__(256) k3_tower1(const float* __restrict__ W1,
                                                 const float* __restrict__ b1) {
    __shared__ float As[128][33];
    __shared__ float Bs[32][64];
    __shared__ float csum[64];
    __shared__ float csq[64];
    const int tid = threadIdx.x;
    const int tx = tid & 15, ty = tid >> 4;
    const int d = blockIdx.y;
    const int r0 = blockIdx.x * 128;
    if (tid < 64) { csum[tid] = 0.f; csq[tid] = 0.f; }

    float acc[8][4];
#pragma unroll
    for (int rr = 0; rr < 8; rr++)
#pragma unroll
        for (int cc = 0; cc < 4; cc++) acc[rr][cc] = 0.f;

    const float* W1d = W1 + (size_t)d * A3 * A3;
    for (int k0 = 0; k0 < A3; k0 += 32) {
#pragma unroll
        for (int i = 0; i < 4; i++) {
            int idx = tid + i * 256;
            int row = idx >> 3, kq = idx & 7;
            float4 v = *(const float4*)&g_rep[(size_t)(r0 + row) * A3 + k0 + kq * 4];
            As[row][kq * 4 + 0] = v.x; As[row][kq * 4 + 1] = v.y;
            As[row][kq * 4 + 2] = v.z; As[row][kq * 4 + 3] = v.w;
        }
#pragma unroll
        for (int i = 0; i < 2; i++) {
            int idx = tid + i * 256;
            int row = idx >> 4, kq = idx & 15;
            *(float4*)&Bs[row][kq * 4] =
                *(const float4*)&W1d[(size_t)(k0 + row) * A3 + kq * 4];
        }
        __syncthreads();
#pragma unroll 8
        for (int k = 0; k < 32; k++) {
            float4 bv = *(const float4*)&Bs[k][tx * 4];
            float b0 = bv.x, b1v = bv.y, b2 = bv.z, b3 = bv.w;
            float a[8];
#pragma unroll
            for (int rr = 0; rr < 8; rr++) a[rr] = As[ty * 8 + rr][k];
#pragma unroll
            for (int rr = 0; rr < 8; rr++) {
                acc[rr][0] += a[rr] * b0; acc[rr][1] += a[rr] * b1v;
                acc[rr][2] += a[rr] * b2; acc[rr][3] += a[rr] * b3;
            }
        }
        __syncthreads();
    }
    float4 bv = *(const float4*)&b1[d * A3 + tx * 4];
    float bb[4] = {bv.x, bv.y, bv.z, bv.w};
    float ls[4] = {0, 0, 0, 0}, lq[4] = {0, 0, 0, 0};
#pragma unroll
    for (int rr = 0; rr < 8; rr++) {
        float v0 = acc[rr][0] + bb[0], v1 = acc[rr][1] + bb[1];
        float v2 = acc[rr][2] + bb[2], v3 = acc[rr][3] + bb[3];
        *(float4*)&g_h[((size_t)d * NROWS + r0 + ty * 8 + rr) * A3 + tx * 4] =
            make_float4(v0, v1, v2, v3);
        ls[0] += v0; lq[0] += v0 * v0; ls[1] += v1; lq[1] += v1 * v1;
        ls[2] += v2; lq[2] += v2 * v2; ls[3] += v3; lq[3] += v3 * v3;
    }
#pragma unroll
    for (int cc = 0; cc < 4; cc++) {
        atomicAdd(&csum[tx * 4 + cc], ls[cc]);
        atomicAdd(&csq [tx * 4 + cc], lq[cc]);
    }
    __syncthreads();
    if (tid < 64) {
        atomicAdd(&g_sum[d * A3 + tid], csum[tid]);
        atomicAdd(&g_sq [d * A3 + tid], csq [tid]);
    }
}

// ---------------- K4: finalize BN -> fused scale/shift -----------------------
__global__ void k4_stats(const float* __restrict__ gamma,
                         const float* __restrict__ beta) {
    int i = threadIdx.x;
    if (i < DTOW * A3) {
        const float inv_n = 1.0f / (float)NROWS;
        float mean = g_sum[i] * inv_n;
        float var  = g_sq[i] * inv_n - mean * mean;   // biased, like torch BN
        float is   = rsqrtf(var + 1e-5f);
        float sc   = is * gamma[i];
        g_scale[i] = sc;
        g_shift[i] = beta[i] - mean * sc;
    }
}

// ---------------- K5: y[d] = elu(norm(h[d])) @ W2[d] + b2[d] -> g_y (contig) -
__global__ void __launch_bounds__(256) k5_tower2(const float* __restrict__ W2,
                                                 const float* __restrict__ b2) {
    __shared__ float hs[128][33];
    __shared__ float W2s[32][96];
    const int tid = threadIdx.x;
    const int tx = tid & 15, ty = tid >> 4;
    const int d = blockIdx.y;
    const int r0 = blockIdx.x * 128;

    float acc[8][6];
#pragma unroll
    for (int rr = 0; rr < 8; rr++)
#pragma unroll
        for (int cc = 0; cc < 6; cc++) acc[rr][cc] = 0.f;

    const float* W2d = W2 + (size_t)d * A3 * PLEN;
    for (int k0 = 0; k0 < A3; k0 += 32) {
        // h chunk with fused affine + ELU (128 x 32 = 1024 float4, 4/thread)
#pragma unroll
        for (int i = 0; i < 4; i++) {
            int idx = tid + i * 256;
            int row = idx >> 3, kq = idx & 7;
            float4 v  = *(const float4*)&g_h[((size_t)d * NROWS + r0 + row) * A3 + k0 + kq * 4];
            float4 sc = *(const float4*)&g_scale[d * A3 + k0 + kq * 4];
            float4 sh = *(const float4*)&g_shift[d * A3 + k0 + kq * 4];
            float t0 = v.x * sc.x + sh.x; t0 = t0 > 0.f ? t0 : expm1f(t0);
            float t1 = v.y * sc.y + sh.y; t1 = t1 > 0.f ? t1 : expm1f(t1);
            float t2 = v.z * sc.z + sh.z; t2 = t2 > 0.f ? t2 : expm1f(t2);
            float t3 = v.w * sc.w + sh.w; t3 = t3 > 0.f ? t3 : expm1f(t3);
            hs[row][kq * 4 + 0] = t0; hs[row][kq * 4 + 1] = t1;
            hs[row][kq * 4 + 2] = t2; hs[row][kq * 4 + 3] = t3;
        }
        // W2 chunk: 32 x 96 (768 float4, 3/thread)
#pragma unroll
        for (int i = 0; i < 3; i++) {
            int idx = tid + i * 256;
            int row = idx / 24, pq = idx % 24;
            *(float4*)&W2s[row][pq * 4] =
                *(const float4*)&W2d[(size_t)(k0 + row) * PLEN + pq * 4];
        }
        __syncthreads();
#pragma unroll 8
        for (int k = 0; k < 32; k++) {
            float a[8], b[6];
#pragma unroll
            for (int rr = 0; rr < 8; rr++) a[rr] = hs[ty * 8 + rr][k];
#pragma unroll
            for (int cc = 0; cc < 6; cc++) b[cc] = W2s[k][tx * 6 + cc];
#pragma unroll
            for (int rr = 0; rr < 8; rr++)
#pragma unroll
                for (int cc = 0; cc < 6; cc++) acc[rr][cc] += a[rr] * b[cc];
        }
        __syncthreads();
    }
    float bb[6];
#pragma unroll
    for (int cc = 0; cc < 6; cc++) bb[cc] = b2[d * PLEN + tx * 6 + cc];
#pragma unroll
    for (int rr = 0; rr < 8; rr++) {
        size_t rowoff = ((size_t)d * NROWS + r0 + ty * 8 + rr) * PLEN;
#pragma unroll
        for (int cc = 0; cc < 6; cc++)
            g_y[rowoff + tx * 6 + cc] = acc[rr][cc] + bb[cc];
    }
}

// ---------------- K6: out[n, p*8+d] = g_y[d][n][p] ---------------------------
// n*768 + p*8 = 8*(n*96+p) -> pure [D, M] -> [M, D] transpose, fully coalesced.
__global__ void __launch_bounds__(256) k6_interleave(float* __restrict__ out) {
    const size_t M = (size_t)NROWS * PLEN;
    size_t g = (size_t)blockIdx.x * 256 + threadIdx.x;
    float v[8];
#pragma unroll
    for (int d = 0; d < 8; d++) v[d] = g_y[(size_t)d * M + g];
    float4* o = (float4*)out;
    o[2 * g]     = make_float4(v[0], v[1], v[2], v[3]);
    o[2 * g + 1] = make_float4(v[4], v[5], v[6], v[7]);
}

// ---------------- launch ------------------------------------------------------
extern "C" void kernel_launch(void* const* d_in, const int* in_sizes, int n_in,
                              void* d_out, int out_size) {
    const float* x     = (const float*)d_in[0];
    const float* shu   = (const float*)d_in[1];
    const float* lw    = (const float*)d_in[2];
    const float* lb    = (const float*)d_in[3];
    const float* W1    = (const float*)d_in[4];
    const float* b1    = (const float*)d_in[5];
    const float* gamma = (const float*)d_in[6];
    const float* beta  = (const float*)d_in[7];
    const float* W2    = (const float*)d_in[8];
    const float* b2    = (const float*)d_in[9];
    float* out = (float*)d_out;

    // second returned array (rep) concatenated after y_1, if the harness wants it
    float* rep_out = ((size_t)out_size >= (size_t)NROWS * (PLEN * DTOW + A3))
                         ? out + (size_t)NROWS * PLEN * DTOW
                         : nullptr;

    k1_gemm_norm<<<NROWS / 128, 256>>>(x, shu);
    k2_window<<<NROWS / 128, 256>>>(lw, lb, rep_out);
    kz_zero<<<1, 512>>>();
    k3_tower1<<<dim3(NROWS / 128, DTOW), 256>>>(W1, b1);
    k4_stats<<<1, 512>>>(gamma, beta);
    k5_tower2<<<dim3(NROWS / 128, DTOW), 256>>>(W2, b2);
    k6_interleave<<<(NROWS * PLEN) / 256, 256>>>(out);
}